// round 1
// baseline (speedup 1.0000x reference)
#include <cuda_runtime.h>
#include <math.h>
#include <stdint.h>

// Problem constants
#define B_    8
#define N_    1024
#define DM    1024
#define H_    16
#define DK    64
#define MROWS (B_ * N_)          // 8192
#define EPS_  1e-9f

// ---------------- scratch (device globals; no allocations allowed) ----------
__device__ float g_Q  [B_ * H_ * N_ * DK];   // [b,h,n,d]
__device__ float g_K  [B_ * H_ * N_ * DK];
__device__ float g_V  [B_ * H_ * N_ * DK];
__device__ float g_XW [MROWS * DM];          // queries @ Wb, row-major [b*n, d]
__device__ float g_CAT[MROWS * DM];          // attention output, [b, n, h*dv]

// ---------------------------------------------------------------------------
// Generic 64x64 tile fp32 GEMM, BK=16, 256 threads, 4x4 per thread.
// WNK=true : W is [N,K] row-major (C = A @ W^T)
// WNK=false: W is [K,N] row-major (C = A @ W)
// OMODE=0  : C row-major [M,N]
// OMODE=1  : scatter to head layout [b,h,tok,d] (m=b*1024+tok, n=h*64+d)
// ---------------------------------------------------------------------------
template<bool WNK, bool HASB, int OMODE>
__global__ __launch_bounds__(256, 4)
void gemm64(const float* __restrict__ A, const float* __restrict__ W,
            const float* __restrict__ bias, float* __restrict__ C,
            int M, int Nn, int K)
{
    __shared__ float As[16][64];
    __shared__ float Ws[16][64];
    const int tid = threadIdx.x;
    const int m0 = blockIdx.y * 64;
    const int n0 = blockIdx.x * 64;
    const int rm = (tid >> 4) << 2;
    const int rn = (tid & 15) << 2;
    const int lrow = tid >> 2;          // 0..63
    const int lkq  = (tid & 3) << 2;    // 0,4,8,12
    const int wkr  = tid >> 4;          // 0..15
    const int wnq  = (tid & 15) << 2;   // 0..60

    float acc[4][4] = {};

    for (int k0 = 0; k0 < K; k0 += 16) {
        float4 av = *(const float4*)(A + (size_t)(m0 + lrow) * K + k0 + lkq);
        As[lkq + 0][lrow] = av.x; As[lkq + 1][lrow] = av.y;
        As[lkq + 2][lrow] = av.z; As[lkq + 3][lrow] = av.w;
        if (WNK) {
            float4 wv = *(const float4*)(W + (size_t)(n0 + lrow) * K + k0 + lkq);
            Ws[lkq + 0][lrow] = wv.x; Ws[lkq + 1][lrow] = wv.y;
            Ws[lkq + 2][lrow] = wv.z; Ws[lkq + 3][lrow] = wv.w;
        } else {
            float4 wv = *(const float4*)(W + (size_t)(k0 + wkr) * Nn + n0 + wnq);
            *(float4*)&Ws[wkr][wnq] = wv;
        }
        __syncthreads();
#pragma unroll
        for (int kk = 0; kk < 16; kk++) {
            float4 a = *(const float4*)&As[kk][rm];
            float4 b = *(const float4*)&Ws[kk][rn];
            float ar[4] = {a.x, a.y, a.z, a.w};
            float br[4] = {b.x, b.y, b.z, b.w};
#pragma unroll
            for (int i = 0; i < 4; i++)
#pragma unroll
                for (int j = 0; j < 4; j++)
                    acc[i][j] += ar[i] * br[j];
        }
        __syncthreads();
    }

#pragma unroll
    for (int i = 0; i < 4; i++) {
        const int m = m0 + rm + i;
#pragma unroll
        for (int j = 0; j < 4; j++) {
            const int n = n0 + rn + j;
            float v = acc[i][j];
            if (HASB) v += bias[n];
            if (OMODE == 0) {
                C[(size_t)m * Nn + n] = v;
            } else {
                const int bb  = m >> 10, tok = m & 1023;
                const int hh  = n >> 6,  dd  = n & 63;
                C[((((size_t)bb * H_ + hh) * N_) + tok) * DK + dd] = v;
            }
        }
    }
}

// ---------------------------------------------------------------------------
// P[b,q,k] = sigmoid( dot(xW[b,q,:], queries[b,k,:]) + bb )   (batched NT)
// ---------------------------------------------------------------------------
__global__ __launch_bounds__(256, 4)
void gemm_phrasal(const float* __restrict__ XW, const float* __restrict__ Qin,
                  const float* __restrict__ bbv, float* __restrict__ Pout)
{
    __shared__ float As[16][64];
    __shared__ float Ws[16][64];
    const int bz = blockIdx.z;
    const float* A = XW  + (size_t)bz * N_ * DM;
    const float* W = Qin + (size_t)bz * N_ * DM;
    const float bb0 = bbv[0];

    const int tid = threadIdx.x;
    const int m0 = blockIdx.y * 64;
    const int n0 = blockIdx.x * 64;
    const int rm = (tid >> 4) << 2;
    const int rn = (tid & 15) << 2;
    const int lrow = tid >> 2;
    const int lkq  = (tid & 3) << 2;

    float acc[4][4] = {};
    for (int k0 = 0; k0 < DM; k0 += 16) {
        float4 av = *(const float4*)(A + (size_t)(m0 + lrow) * DM + k0 + lkq);
        As[lkq + 0][lrow] = av.x; As[lkq + 1][lrow] = av.y;
        As[lkq + 2][lrow] = av.z; As[lkq + 3][lrow] = av.w;
        float4 wv = *(const float4*)(W + (size_t)(n0 + lrow) * DM + k0 + lkq);
        Ws[lkq + 0][lrow] = wv.x; Ws[lkq + 1][lrow] = wv.y;
        Ws[lkq + 2][lrow] = wv.z; Ws[lkq + 3][lrow] = wv.w;
        __syncthreads();
#pragma unroll
        for (int kk = 0; kk < 16; kk++) {
            float4 a = *(const float4*)&As[kk][rm];
            float4 b = *(const float4*)&Ws[kk][rn];
            float ar[4] = {a.x, a.y, a.z, a.w};
            float br[4] = {b.x, b.y, b.z, b.w};
#pragma unroll
            for (int i = 0; i < 4; i++)
#pragma unroll
                for (int j = 0; j < 4; j++)
                    acc[i][j] += ar[i] * br[j];
        }
        __syncthreads();
    }
#pragma unroll
    for (int i = 0; i < 4; i++) {
        const int m = m0 + rm + i;
#pragma unroll
        for (int j = 0; j < 4; j++) {
            const int n = n0 + rn + j;
            float s = acc[i][j] + bb0;
            float p = 1.0f / (1.0f + __expf(-s));
            Pout[((size_t)bz * N_ + m) * N_ + n] = p;
        }
    }
}

// ---------------------------------------------------------------------------
// logits[b,h,q,k] = 0.125*dot(Qh[q],Kh[k]) + lambda*log(P[b,q,k]+eps)
// z = b*H + h ; K-dim = 64
// ---------------------------------------------------------------------------
__global__ __launch_bounds__(256, 4)
void gemm_logits(const float* __restrict__ P, const float* __restrict__ lam_p,
                 float* __restrict__ att)
{
    __shared__ float As[16][64];
    __shared__ float Ws[16][64];
    const int z = blockIdx.z;
    const int bz = z >> 4;
    const float* A = g_Q + (size_t)z * N_ * DK;
    const float* W = g_K + (size_t)z * N_ * DK;
    const float lam = lam_p[0];

    const int tid = threadIdx.x;
    const int m0 = blockIdx.y * 64;
    const int n0 = blockIdx.x * 64;
    const int rm = (tid >> 4) << 2;
    const int rn = (tid & 15) << 2;
    const int lrow = tid >> 2;
    const int lkq  = (tid & 3) << 2;

    float acc[4][4] = {};
#pragma unroll
    for (int k0 = 0; k0 < DK; k0 += 16) {
        float4 av = *(const float4*)(A + (size_t)(m0 + lrow) * DK + k0 + lkq);
        As[lkq + 0][lrow] = av.x; As[lkq + 1][lrow] = av.y;
        As[lkq + 2][lrow] = av.z; As[lkq + 3][lrow] = av.w;
        float4 wv = *(const float4*)(W + (size_t)(n0 + lrow) * DK + k0 + lkq);
        Ws[lkq + 0][lrow] = wv.x; Ws[lkq + 1][lrow] = wv.y;
        Ws[lkq + 2][lrow] = wv.z; Ws[lkq + 3][lrow] = wv.w;
        __syncthreads();
#pragma unroll
        for (int kk = 0; kk < 16; kk++) {
            float4 a = *(const float4*)&As[kk][rm];
            float4 b = *(const float4*)&Ws[kk][rn];
            float ar[4] = {a.x, a.y, a.z, a.w};
            float br[4] = {b.x, b.y, b.z, b.w};
#pragma unroll
            for (int i = 0; i < 4; i++)
#pragma unroll
                for (int j = 0; j < 4; j++)
                    acc[i][j] += ar[i] * br[j];
        }
        __syncthreads();
    }
#pragma unroll
    for (int i = 0; i < 4; i++) {
        const int m = m0 + rm + i;
#pragma unroll
        for (int j = 0; j < 4; j++) {
            const int n = n0 + rn + j;
            float pv = P[((size_t)bz * N_ + m) * N_ + n];
            float v = acc[i][j] * 0.125f + lam * __logf(pv + EPS_);
            att[((size_t)z * N_ + m) * N_ + n] = v;
        }
    }
}

// ---------------------------------------------------------------------------
// In-place row softmax over att: 131072 rows x 1024. Warp per row.
// ---------------------------------------------------------------------------
__global__ __launch_bounds__(256)
void softmax_rows(float* __restrict__ att)
{
    const size_t row = (size_t)blockIdx.x * 8 + (threadIdx.x >> 5);
    const int lane = threadIdx.x & 31;
    float4* p4 = (float4*)(att + row * 1024);

    float4 v[8];
    float mx = -3.4e38f;
#pragma unroll
    for (int i = 0; i < 8; i++) {
        v[i] = p4[lane + 32 * i];
        mx = fmaxf(mx, fmaxf(fmaxf(v[i].x, v[i].y), fmaxf(v[i].z, v[i].w)));
    }
#pragma unroll
    for (int o = 16; o > 0; o >>= 1)
        mx = fmaxf(mx, __shfl_xor_sync(0xffffffffu, mx, o));

    float s = 0.0f;
#pragma unroll
    for (int i = 0; i < 8; i++) {
        v[i].x = __expf(v[i].x - mx);
        v[i].y = __expf(v[i].y - mx);
        v[i].z = __expf(v[i].z - mx);
        v[i].w = __expf(v[i].w - mx);
        s += v[i].x + v[i].y + v[i].z + v[i].w;
    }
#pragma unroll
    for (int o = 16; o > 0; o >>= 1)
        s += __shfl_xor_sync(0xffffffffu, s, o);

    const float inv = 1.0f / s;
#pragma unroll
    for (int i = 0; i < 8; i++) {
        v[i].x *= inv; v[i].y *= inv; v[i].z *= inv; v[i].w *= inv;
        p4[lane + 32 * i] = v[i];
    }
}

// ---------------------------------------------------------------------------
// CAT[b, q, h*64+d] = sum_k att[b,h,q,k] * V[b,h,k,d]   (z = b*H+h)
// M=1024, N=64, K=1024
// ---------------------------------------------------------------------------
__global__ __launch_bounds__(256, 4)
void gemm_av(const float* __restrict__ att, float* __restrict__ CAT)
{
    __shared__ float As[16][64];
    __shared__ float Ws[16][64];
    const int z = blockIdx.z;
    const int bz = z >> 4;
    const int hz = z & 15;
    const float* A = att + (size_t)z * N_ * N_;   // [1024,1024]
    const float* W = g_V + (size_t)z * N_ * DK;   // [1024,64] (k rows, d contiguous)

    const int tid = threadIdx.x;
    const int m0 = blockIdx.y * 64;
    const int rm = (tid >> 4) << 2;
    const int rn = (tid & 15) << 2;
    const int lrow = tid >> 2;
    const int lkq  = (tid & 3) << 2;
    const int wkr  = tid >> 4;
    const int wnq  = (tid & 15) << 2;

    float acc[4][4] = {};
    for (int k0 = 0; k0 < N_; k0 += 16) {
        float4 av = *(const float4*)(A + (size_t)(m0 + lrow) * N_ + k0 + lkq);
        As[lkq + 0][lrow] = av.x; As[lkq + 1][lrow] = av.y;
        As[lkq + 2][lrow] = av.z; As[lkq + 3][lrow] = av.w;
        float4 wv = *(const float4*)(W + (size_t)(k0 + wkr) * DK + wnq);
        *(float4*)&Ws[wkr][wnq] = wv;
        __syncthreads();
#pragma unroll
        for (int kk = 0; kk < 16; kk++) {
            float4 a = *(const float4*)&As[kk][rm];
            float4 b = *(const float4*)&Ws[kk][rn];
            float ar[4] = {a.x, a.y, a.z, a.w};
            float br[4] = {b.x, b.y, b.z, b.w};
#pragma unroll
            for (int i = 0; i < 4; i++)
#pragma unroll
                for (int j = 0; j < 4; j++)
                    acc[i][j] += ar[i] * br[j];
        }
        __syncthreads();
    }
#pragma unroll
    for (int i = 0; i < 4; i++) {
        const int m = m0 + rm + i;
#pragma unroll
        for (int j = 0; j < 4; j++) {
            const int n = rn + j;   // d in [0,64)
            CAT[((size_t)bz * N_ + m) * DM + hz * DK + n] = acc[i][j];
        }
    }
}

// ---------------------------------------------------------------------------
extern "C" void kernel_launch(void* const* d_in, const int* in_sizes, int n_in,
                              void* d_out, int out_size)
{
    const float* queries = (const float*)d_in[0];
    const float* keys    = (const float*)d_in[1];
    const float* values  = (const float*)d_in[2];
    const float* Wq = (const float*)d_in[3];
    const float* bq = (const float*)d_in[4];
    const float* Wk = (const float*)d_in[5];
    const float* bk = (const float*)d_in[6];
    const float* Wv = (const float*)d_in[7];
    const float* bv = (const float*)d_in[8];
    const float* Wo = (const float*)d_in[9];
    const float* bo = (const float*)d_in[10];
    const float* Wb = (const float*)d_in[11];
    const float* bb = (const float*)d_in[12];
    const float* lam = (const float*)d_in[13];

    // Output tuple (out, att, P), concatenated.
    float* out_main = (float*)d_out;                       // 8*1024*1024
    float* att      = out_main + (size_t)B_ * N_ * DM;     // 8*16*1024*1024
    float* Pout     = att + (size_t)B_ * H_ * N_ * N_;     // 8*1024*1024

    float *gQ, *gK, *gV, *gXW, *gCAT;
    cudaGetSymbolAddress((void**)&gQ,  g_Q);
    cudaGetSymbolAddress((void**)&gK,  g_K);
    cudaGetSymbolAddress((void**)&gV,  g_V);
    cudaGetSymbolAddress((void**)&gXW, g_XW);
    cudaGetSymbolAddress((void**)&gCAT, g_CAT);

    dim3 blk(256);
    dim3 gProj(DM / 64, MROWS / 64);          // 16 x 128

    // QKV projections (NT, bias, head-scatter)
    gemm64<true,  true,  1><<<gProj, blk>>>(queries, Wq, bq, gQ, MROWS, DM, DM);
    gemm64<true,  true,  1><<<gProj, blk>>>(keys,    Wk, bk, gK, MROWS, DM, DM);
    gemm64<true,  true,  1><<<gProj, blk>>>(values,  Wv, bv, gV, MROWS, DM, DM);
    // xW = queries @ Wb (NN, no bias)
    gemm64<false, false, 0><<<gProj, blk>>>(queries, Wb, nullptr, gXW, MROWS, DM, DM);

    // P = sigmoid(xW @ queries^T + bb)  -> d_out P region
    gemm_phrasal<<<dim3(N_ / 64, N_ / 64, B_), blk>>>(gXW, queries, bb, Pout);

    // logits -> att region
    gemm_logits<<<dim3(N_ / 64, N_ / 64, B_ * H_), blk>>>(Pout, lam, att);

    // softmax in-place on att
    softmax_rows<<<(B_ * H_ * N_) / 8, blk>>>(att);

    // att @ V -> CAT
    gemm_av<<<dim3(1, N_ / 64, B_ * H_), blk>>>(att, gCAT);

    // out = CAT @ Wo^T + bo
    gemm64<true, true, 0><<<gProj, blk>>>(gCAT, Wo, bo, out_main, MROWS, DM, DM);

    (void)in_sizes; (void)n_in; (void)out_size;
}

// round 2
// speedup vs baseline: 1.0004x; 1.0004x over previous
#include <cuda_runtime.h>
#include <math.h>
#include <stdint.h>

// Problem constants
#define B_    8
#define N_    1024
#define DM    1024
#define H_    16
#define DK    64
#define MROWS (B_ * N_)          // 8192
#define EPS_  1e-9f

// ---------------- scratch (device globals; no allocations allowed) ----------
__device__ float g_Q  [B_ * H_ * N_ * DK];   // [b,h,n,d]
__device__ float g_K  [B_ * H_ * N_ * DK];
__device__ float g_V  [B_ * H_ * N_ * DK];
__device__ float g_XW [MROWS * DM];          // queries @ Wb, row-major [b*n, d]
__device__ float g_CAT[MROWS * DM];          // attention output, [b, n, h*dv]

// ---------------------------------------------------------------------------
// Generic 64x64 tile fp32 GEMM, BK=16, 256 threads, 4x4 per thread.
// WNK=true : W is [N,K] row-major (C = A @ W^T)
// WNK=false: W is [K,N] row-major (C = A @ W)
// OMODE=0  : C row-major [M,N]
// OMODE=1  : scatter to head layout [b,h,tok,d] (m=b*1024+tok, n=h*64+d)
// ---------------------------------------------------------------------------
template<bool WNK, bool HASB, int OMODE>
__global__ __launch_bounds__(256, 4)
void gemm64(const float* __restrict__ A, const float* __restrict__ W,
            const float* __restrict__ bias, float* __restrict__ C,
            int M, int Nn, int K)
{
    __shared__ float As[16][64];
    __shared__ float Ws[16][64];
    const int tid = threadIdx.x;
    const int m0 = blockIdx.y * 64;
    const int n0 = blockIdx.x * 64;
    const int rm = (tid >> 4) << 2;
    const int rn = (tid & 15) << 2;
    const int lrow = tid >> 2;          // 0..63
    const int lkq  = (tid & 3) << 2;    // 0,4,8,12
    const int wkr  = tid >> 4;          // 0..15
    const int wnq  = (tid & 15) << 2;   // 0..60

    float acc[4][4] = {};

    for (int k0 = 0; k0 < K; k0 += 16) {
        float4 av = *(const float4*)(A + (size_t)(m0 + lrow) * K + k0 + lkq);
        As[lkq + 0][lrow] = av.x; As[lkq + 1][lrow] = av.y;
        As[lkq + 2][lrow] = av.z; As[lkq + 3][lrow] = av.w;
        if (WNK) {
            float4 wv = *(const float4*)(W + (size_t)(n0 + lrow) * K + k0 + lkq);
            Ws[lkq + 0][lrow] = wv.x; Ws[lkq + 1][lrow] = wv.y;
            Ws[lkq + 2][lrow] = wv.z; Ws[lkq + 3][lrow] = wv.w;
        } else {
            float4 wv = *(const float4*)(W + (size_t)(k0 + wkr) * Nn + n0 + wnq);
            *(float4*)&Ws[wkr][wnq] = wv;
        }
        __syncthreads();
#pragma unroll
        for (int kk = 0; kk < 16; kk++) {
            float4 a = *(const float4*)&As[kk][rm];
            float4 b = *(const float4*)&Ws[kk][rn];
            float ar[4] = {a.x, a.y, a.z, a.w};
            float br[4] = {b.x, b.y, b.z, b.w};
#pragma unroll
            for (int i = 0; i < 4; i++)
#pragma unroll
                for (int j = 0; j < 4; j++)
                    acc[i][j] += ar[i] * br[j];
        }
        __syncthreads();
    }

#pragma unroll
    for (int i = 0; i < 4; i++) {
        const int m = m0 + rm + i;
#pragma unroll
        for (int j = 0; j < 4; j++) {
            const int n = n0 + rn + j;
            float v = acc[i][j];
            if (HASB) v += bias[n];
            if (OMODE == 0) {
                C[(size_t)m * Nn + n] = v;
            } else {
                const int bb  = m >> 10, tok = m & 1023;
                const int hh  = n >> 6,  dd  = n & 63;
                C[((((size_t)bb * H_ + hh) * N_) + tok) * DK + dd] = v;
            }
        }
    }
}

// ---------------------------------------------------------------------------
// P[b,q,k] = sigmoid( dot(xW[b,q,:], queries[b,k,:]) + bb )   (batched NT)
// ---------------------------------------------------------------------------
__global__ __launch_bounds__(256, 4)
void gemm_phrasal(const float* __restrict__ XW, const float* __restrict__ Qin,
                  const float* __restrict__ bbv, float* __restrict__ Pout)
{
    __shared__ float As[16][64];
    __shared__ float Ws[16][64];
    const int bz = blockIdx.z;
    const float* A = XW  + (size_t)bz * N_ * DM;
    const float* W = Qin + (size_t)bz * N_ * DM;
    const float bb0 = bbv[0];

    const int tid = threadIdx.x;
    const int m0 = blockIdx.y * 64;
    const int n0 = blockIdx.x * 64;
    const int rm = (tid >> 4) << 2;
    const int rn = (tid & 15) << 2;
    const int lrow = tid >> 2;
    const int lkq  = (tid & 3) << 2;

    float acc[4][4] = {};
    for (int k0 = 0; k0 < DM; k0 += 16) {
        float4 av = *(const float4*)(A + (size_t)(m0 + lrow) * DM + k0 + lkq);
        As[lkq + 0][lrow] = av.x; As[lkq + 1][lrow] = av.y;
        As[lkq + 2][lrow] = av.z; As[lkq + 3][lrow] = av.w;
        float4 wv = *(const float4*)(W + (size_t)(n0 + lrow) * DM + k0 + lkq);
        Ws[lkq + 0][lrow] = wv.x; Ws[lkq + 1][lrow] = wv.y;
        Ws[lkq + 2][lrow] = wv.z; Ws[lkq + 3][lrow] = wv.w;
        __syncthreads();
#pragma unroll
        for (int kk = 0; kk < 16; kk++) {
            float4 a = *(const float4*)&As[kk][rm];
            float4 b = *(const float4*)&Ws[kk][rn];
            float ar[4] = {a.x, a.y, a.z, a.w};
            float br[4] = {b.x, b.y, b.z, b.w};
#pragma unroll
            for (int i = 0; i < 4; i++)
#pragma unroll
                for (int j = 0; j < 4; j++)
                    acc[i][j] += ar[i] * br[j];
        }
        __syncthreads();
    }
#pragma unroll
    for (int i = 0; i < 4; i++) {
        const int m = m0 + rm + i;
#pragma unroll
        for (int j = 0; j < 4; j++) {
            const int n = n0 + rn + j;
            float s = acc[i][j] + bb0;
            float p = 1.0f / (1.0f + __expf(-s));
            Pout[((size_t)bz * N_ + m) * N_ + n] = p;
        }
    }
}

// ---------------------------------------------------------------------------
// logits[b,h,q,k] = 0.125*dot(Qh[q],Kh[k]) + lambda*log(P[b,q,k]+eps)
// z = b*H + h ; K-dim = 64
// ---------------------------------------------------------------------------
__global__ __launch_bounds__(256, 4)
void gemm_logits(const float* __restrict__ P, const float* __restrict__ lam_p,
                 float* __restrict__ att)
{
    __shared__ float As[16][64];
    __shared__ float Ws[16][64];
    const int z = blockIdx.z;
    const int bz = z >> 4;
    const float* A = g_Q + (size_t)z * N_ * DK;
    const float* W = g_K + (size_t)z * N_ * DK;
    const float lam = lam_p[0];

    const int tid = threadIdx.x;
    const int m0 = blockIdx.y * 64;
    const int n0 = blockIdx.x * 64;
    const int rm = (tid >> 4) << 2;
    const int rn = (tid & 15) << 2;
    const int lrow = tid >> 2;
    const int lkq  = (tid & 3) << 2;

    float acc[4][4] = {};
#pragma unroll
    for (int k0 = 0; k0 < DK; k0 += 16) {
        float4 av = *(const float4*)(A + (size_t)(m0 + lrow) * DK + k0 + lkq);
        As[lkq + 0][lrow] = av.x; As[lkq + 1][lrow] = av.y;
        As[lkq + 2][lrow] = av.z; As[lkq + 3][lrow] = av.w;
        float4 wv = *(const float4*)(W + (size_t)(n0 + lrow) * DK + k0 + lkq);
        Ws[lkq + 0][lrow] = wv.x; Ws[lkq + 1][lrow] = wv.y;
        Ws[lkq + 2][lrow] = wv.z; Ws[lkq + 3][lrow] = wv.w;
        __syncthreads();
#pragma unroll
        for (int kk = 0; kk < 16; kk++) {
            float4 a = *(const float4*)&As[kk][rm];
            float4 b = *(const float4*)&Ws[kk][rn];
            float ar[4] = {a.x, a.y, a.z, a.w};
            float br[4] = {b.x, b.y, b.z, b.w};
#pragma unroll
            for (int i = 0; i < 4; i++)
#pragma unroll
                for (int j = 0; j < 4; j++)
                    acc[i][j] += ar[i] * br[j];
        }
        __syncthreads();
    }
#pragma unroll
    for (int i = 0; i < 4; i++) {
        const int m = m0 + rm + i;
#pragma unroll
        for (int j = 0; j < 4; j++) {
            const int n = n0 + rn + j;
            float pv = P[((size_t)bz * N_ + m) * N_ + n];
            float v = acc[i][j] * 0.125f + lam * __logf(pv + EPS_);
            att[((size_t)z * N_ + m) * N_ + n] = v;
        }
    }
}

// ---------------------------------------------------------------------------
// In-place row softmax over att: 131072 rows x 1024. Warp per row.
// ---------------------------------------------------------------------------
__global__ __launch_bounds__(256)
void softmax_rows(float* __restrict__ att)
{
    const size_t row = (size_t)blockIdx.x * 8 + (threadIdx.x >> 5);
    const int lane = threadIdx.x & 31;
    float4* p4 = (float4*)(att + row * 1024);

    float4 v[8];
    float mx = -3.4e38f;
#pragma unroll
    for (int i = 0; i < 8; i++) {
        v[i] = p4[lane + 32 * i];
        mx = fmaxf(mx, fmaxf(fmaxf(v[i].x, v[i].y), fmaxf(v[i].z, v[i].w)));
    }
#pragma unroll
    for (int o = 16; o > 0; o >>= 1)
        mx = fmaxf(mx, __shfl_xor_sync(0xffffffffu, mx, o));

    float s = 0.0f;
#pragma unroll
    for (int i = 0; i < 8; i++) {
        v[i].x = __expf(v[i].x - mx);
        v[i].y = __expf(v[i].y - mx);
        v[i].z = __expf(v[i].z - mx);
        v[i].w = __expf(v[i].w - mx);
        s += v[i].x + v[i].y + v[i].z + v[i].w;
    }
#pragma unroll
    for (int o = 16; o > 0; o >>= 1)
        s += __shfl_xor_sync(0xffffffffu, s, o);

    const float inv = 1.0f / s;
#pragma unroll
    for (int i = 0; i < 8; i++) {
        v[i].x *= inv; v[i].y *= inv; v[i].z *= inv; v[i].w *= inv;
        p4[lane + 32 * i] = v[i];
    }
}

// ---------------------------------------------------------------------------
// CAT[b, q, h*64+d] = sum_k att[b,h,q,k] * V[b,h,k,d]   (z = b*H+h)
// M=1024, N=64, K=1024
// ---------------------------------------------------------------------------
__global__ __launch_bounds__(256, 4)
void gemm_av(const float* __restrict__ att, float* __restrict__ CAT)
{
    __shared__ float As[16][64];
    __shared__ float Ws[16][64];
    const int z = blockIdx.z;
    const int bz = z >> 4;
    const int hz = z & 15;
    const float* A = att + (size_t)z * N_ * N_;   // [1024,1024]
    const float* W = g_V + (size_t)z * N_ * DK;   // [1024,64] (k rows, d contiguous)

    const int tid = threadIdx.x;
    const int m0 = blockIdx.y * 64;
    const int rm = (tid >> 4) << 2;
    const int rn = (tid & 15) << 2;
    const int lrow = tid >> 2;
    const int lkq  = (tid & 3) << 2;
    const int wkr  = tid >> 4;
    const int wnq  = (tid & 15) << 2;

    float acc[4][4] = {};
    for (int k0 = 0; k0 < N_; k0 += 16) {
        float4 av = *(const float4*)(A + (size_t)(m0 + lrow) * N_ + k0 + lkq);
        As[lkq + 0][lrow] = av.x; As[lkq + 1][lrow] = av.y;
        As[lkq + 2][lrow] = av.z; As[lkq + 3][lrow] = av.w;
        float4 wv = *(const float4*)(W + (size_t)(k0 + wkr) * DK + wnq);
        *(float4*)&Ws[wkr][wnq] = wv;
        __syncthreads();
#pragma unroll
        for (int kk = 0; kk < 16; kk++) {
            float4 a = *(const float4*)&As[kk][rm];
            float4 b = *(const float4*)&Ws[kk][rn];
            float ar[4] = {a.x, a.y, a.z, a.w};
            float br[4] = {b.x, b.y, b.z, b.w};
#pragma unroll
            for (int i = 0; i < 4; i++)
#pragma unroll
                for (int j = 0; j < 4; j++)
                    acc[i][j] += ar[i] * br[j];
        }
        __syncthreads();
    }
#pragma unroll
    for (int i = 0; i < 4; i++) {
        const int m = m0 + rm + i;
#pragma unroll
        for (int j = 0; j < 4; j++) {
            const int n = rn + j;   // d in [0,64)
            CAT[((size_t)bz * N_ + m) * DM + hz * DK + n] = acc[i][j];
        }
    }
}

// ---------------------------------------------------------------------------
extern "C" void kernel_launch(void* const* d_in, const int* in_sizes, int n_in,
                              void* d_out, int out_size)
{
    const float* queries = (const float*)d_in[0];
    const float* keys    = (const float*)d_in[1];
    const float* values  = (const float*)d_in[2];
    const float* Wq = (const float*)d_in[3];
    const float* bq = (const float*)d_in[4];
    const float* Wk = (const float*)d_in[5];
    const float* bk = (const float*)d_in[6];
    const float* Wv = (const float*)d_in[7];
    const float* bv = (const float*)d_in[8];
    const float* Wo = (const float*)d_in[9];
    const float* bo = (const float*)d_in[10];
    const float* Wb = (const float*)d_in[11];
    const float* bb = (const float*)d_in[12];
    const float* lam = (const float*)d_in[13];

    // Output tuple (out, att, P), concatenated.
    float* out_main = (float*)d_out;                       // 8*1024*1024
    float* att      = out_main + (size_t)B_ * N_ * DM;     // 8*16*1024*1024
    float* Pout     = att + (size_t)B_ * H_ * N_ * N_;     // 8*1024*1024

    float *gQ, *gK, *gV, *gXW, *gCAT;
    cudaGetSymbolAddress((void**)&gQ,  g_Q);
    cudaGetSymbolAddress((void**)&gK,  g_K);
    cudaGetSymbolAddress((void**)&gV,  g_V);
    cudaGetSymbolAddress((void**)&gXW, g_XW);
    cudaGetSymbolAddress((void**)&gCAT, g_CAT);

    dim3 blk(256);
    dim3 gProj(DM / 64, MROWS / 64);          // 16 x 128

    // QKV projections (NT, bias, head-scatter)
    gemm64<true,  true,  1><<<gProj, blk>>>(queries, Wq, bq, gQ, MROWS, DM, DM);
    gemm64<true,  true,  1><<<gProj, blk>>>(keys,    Wk, bk, gK, MROWS, DM, DM);
    gemm64<true,  true,  1><<<gProj, blk>>>(values,  Wv, bv, gV, MROWS, DM, DM);
    // xW = queries @ Wb (NN, no bias)
    gemm64<false, false, 0><<<gProj, blk>>>(queries, Wb, nullptr, gXW, MROWS, DM, DM);

    // P = sigmoid(xW @ queries^T + bb)  -> d_out P region
    gemm_phrasal<<<dim3(N_ / 64, N_ / 64, B_), blk>>>(gXW, queries, bb, Pout);

    // logits -> att region
    gemm_logits<<<dim3(N_ / 64, N_ / 64, B_ * H_), blk>>>(Pout, lam, att);

    // softmax in-place on att
    softmax_rows<<<(B_ * H_ * N_) / 8, blk>>>(att);

    // att @ V -> CAT
    gemm_av<<<dim3(1, N_ / 64, B_ * H_), blk>>>(att, gCAT);

    // out = CAT @ Wo^T + bo
    gemm64<true, true, 0><<<gProj, blk>>>(gCAT, Wo, bo, out_main, MROWS, DM, DM);

    (void)in_sizes; (void)n_in; (void)out_size;
}

// round 4
// speedup vs baseline: 2.4509x; 2.4500x over previous
#include <cuda_runtime.h>
#include <cuda_bf16.h>
#include <stdint.h>
#include <math.h>

#define Bb    8
#define Hh    16
#define NSEQ  1024
#define DMOD  1024
#define DHd   64
#define MR    (Bb * NSEQ)
#define EPSF  1e-9f

typedef unsigned int u32;
typedef unsigned long long u64;

// ------------- scratch (device globals; allocations forbidden) --------------
__device__ float g_Q  [Bb * Hh * NSEQ * DHd];   // [z][tok][d]
__device__ float g_K  [Bb * Hh * NSEQ * DHd];   // [z][tok][d]
__device__ float g_Vt [Bb * Hh * DHd * NSEQ];   // [z][d][tok]  (transposed V)
__device__ float g_XW [MR * DMOD];
__device__ float g_CAT[MR * DMOD];
__device__ float g_L  [Bb * NSEQ * NSEQ];       // lambda*log(P+eps)
__device__ float g_WbT[DMOD * DMOD];            // Wb transposed -> [n][k]

// ------------- helpers -------------------------------------------------------
__device__ __forceinline__ u32 smem_u32(const void* p) {
    u32 a;
    asm("{ .reg .u64 t; cvta.to.shared.u64 t, %1; cvt.u32.u64 %0, t; }"
        : "=r"(a) : "l"(p));
    return a;
}
__device__ __forceinline__ u32 pack2(__nv_bfloat16 a, __nv_bfloat16 b) {
    __nv_bfloat162 t; t.x = a; t.y = b;
    return *reinterpret_cast<u32*>(&t);
}
__device__ __forceinline__ void split1(float v, __nv_bfloat16& h, __nv_bfloat16& l) {
    h = __float2bfloat16(v);
    l = __float2bfloat16(v - __bfloat162float(h));
}
__device__ __forceinline__ void ldm4(u32 addr, u32& r0, u32& r1, u32& r2, u32& r3) {
    asm volatile("ldmatrix.sync.aligned.m8n8.x4.shared.b16 {%0,%1,%2,%3}, [%4];"
                 : "=r"(r0), "=r"(r1), "=r"(r2), "=r"(r3) : "r"(addr));
}
__device__ __forceinline__ void mma16816(float* c, const u32* a, u32 b0, u32 b1) {
    asm volatile(
        "mma.sync.aligned.m16n8k16.row.col.f32.bf16.bf16.f32 "
        "{%0,%1,%2,%3}, {%4,%5,%6,%7}, {%8,%9}, {%0,%1,%2,%3};"
        : "+f"(c[0]), "+f"(c[1]), "+f"(c[2]), "+f"(c[3])
        : "r"(a[0]), "r"(a[1]), "r"(a[2]), "r"(a[3]), "r"(b0), "r"(b1));
}

// ---------------------------------------------------------------------------
// HMMA split-bf16 GEMM: C[128 x NTILE] = A[128xK] @ B[NTILE x K]^T  (NT)
// 256 threads, 8 warps. Block K-chunk = 64. smem tiles swizzled:
//   phys(row,chunk16B) = row*128 + ((chunk ^ (row&7))<<4)
// EPI: 0 proj(bias + head-scatter to [z][tok][d])
//      2 rowmajor     3 phrasal(P=sigmoid(acc+bb); aux=lam*log(P+eps))
//      4 logits(0.125*acc + L[bz])   5 AV scatter to CAT
//      6 rowmajor+bias               7 proj transposed (bias, to [z][d][tok])
// ---------------------------------------------------------------------------
template<int NTILE, int EPI>
__global__ __launch_bounds__(256, 2)
void hmma_gemm(const float* __restrict__ Aptr, const float* __restrict__ Bptr,
               int K, long long sAz, long long sBz,
               float* __restrict__ out0, float* __restrict__ aux,
               const float* __restrict__ bias,
               const float* __restrict__ s0, const float* __restrict__ s1)
{
    constexpr int WN  = (NTILE == 128) ? 4 : 2;   // warps along n
    constexpr int WM  = 8 / WN;                   // warps along m
    constexpr int MT  = 128 / WM;                 // warp m-tile (64 / 32)
    constexpr int NTw = NTILE / WN;               // warp n-tile (32)
    constexpr int MF  = MT / 16;                  // m-frags (4 / 2)
    constexpr int NF  = NTw / 8;                  // n-frags (4)
    constexpr int AHI = 0;
    constexpr int ALO = 128 * 128;                // bytes
    constexpr int BHI = 2 * 128 * 128;
    constexpr int BLO = BHI + NTILE * 128;

    extern __shared__ char smem[];
    const u32 sb = smem_u32(smem);

    const int tid  = threadIdx.x;
    const int wid  = tid >> 5, lane = tid & 31;
    const int wM   = wid % WM, wN = wid / WM;
    const int z    = blockIdx.z;
    const int m0   = blockIdx.y * 128;
    const int n0   = blockIdx.x * NTILE;

    // ldmatrix lane decomposition
    const int mat  = lane >> 3, lir = lane & 7;
    const int rfr  = (mat & 1) * 8 + lir;   // row within 16-row frag
    const int kcf  = mat >> 1;              // 16B k-chunk within k16 step

    const float* Abase = Aptr + (size_t)z * sAz + (size_t)m0 * K;
    const float* Bbase = Bptr + (size_t)z * sBz + (size_t)n0 * K;

    float acc[MF][NF][4];
#pragma unroll
    for (int i = 0; i < MF; i++)
#pragma unroll
        for (int j = 0; j < NF; j++)
#pragma unroll
            for (int e = 0; e < 4; e++) acc[i][j][e] = 0.0f;

    const int C = K >> 6;
    for (int c = 0; c < C; c++) {
        const int k0 = c << 6;
        // ---- stage A (128 rows x 64 k) ----
#pragma unroll
        for (int u = tid; u < 128 * 16; u += 256) {
            const int row = u >> 4, q = u & 15;
            float4 v = ((const float4*)(Abase + (size_t)row * K + k0))[q];
            __nv_bfloat16 h0, h1, h2, h3, l0, l1, l2, l3;
            split1(v.x, h0, l0); split1(v.y, h1, l1);
            split1(v.z, h2, l2); split1(v.w, h3, l3);
            const u32 off = (u32)row * 128 + ((((u32)q >> 1) ^ ((u32)row & 7)) << 4)
                          + ((u32)q & 1) * 8;
            *(uint2*)(smem + AHI + off) = make_uint2(pack2(h0, h1), pack2(h2, h3));
            *(uint2*)(smem + ALO + off) = make_uint2(pack2(l0, l1), pack2(l2, l3));
        }
        // ---- stage B (NTILE rows x 64 k) ----
#pragma unroll
        for (int u = tid; u < NTILE * 16; u += 256) {
            const int row = u >> 4, q = u & 15;
            float4 v = ((const float4*)(Bbase + (size_t)row * K + k0))[q];
            __nv_bfloat16 h0, h1, h2, h3, l0, l1, l2, l3;
            split1(v.x, h0, l0); split1(v.y, h1, l1);
            split1(v.z, h2, l2); split1(v.w, h3, l3);
            const u32 off = (u32)row * 128 + ((((u32)q >> 1) ^ ((u32)row & 7)) << 4)
                          + ((u32)q & 1) * 8;
            *(uint2*)(smem + BHI + off) = make_uint2(pack2(h0, h1), pack2(h2, h3));
            *(uint2*)(smem + BLO + off) = make_uint2(pack2(l0, l1), pack2(l2, l3));
        }
        __syncthreads();

        // ---- compute 4 k16 steps ----
#pragma unroll
        for (int ks = 0; ks < 4; ks++) {
            const u32 kch = (u32)(ks * 2 + kcf);
            u32 ah[MF][4], al[MF][4], bx[NF / 2][4];
            // A rows for this thread's frags
#pragma unroll
            for (int mi = 0; mi < MF; mi++) {
                const u32 row = (u32)(wM * MT + mi * 16 + rfr);
                const u32 ao  = row * 128 + ((kch ^ (row & 7)) << 4);
                ldm4(sb + AHI + ao, ah[mi][0], ah[mi][1], ah[mi][2], ah[mi][3]);
            }
#pragma unroll
            for (int j = 0; j < NF / 2; j++) {
                const u32 row = (u32)(wN * NTw + j * 16 + rfr);
                const u32 bo  = row * 128 + ((kch ^ (row & 7)) << 4);
                ldm4(sb + BHI + bo, bx[j][0], bx[j][1], bx[j][2], bx[j][3]);
            }
            // Ah * Bh
#pragma unroll
            for (int mi = 0; mi < MF; mi++)
#pragma unroll
                for (int ni = 0; ni < NF; ni++)
                    mma16816(acc[mi][ni], ah[mi],
                             bx[ni >> 1][ni & 1], bx[ni >> 1][(ni & 1) + 2]);
            // Al * Bh
#pragma unroll
            for (int mi = 0; mi < MF; mi++) {
                const u32 row = (u32)(wM * MT + mi * 16 + rfr);
                const u32 ao  = row * 128 + ((kch ^ (row & 7)) << 4);
                ldm4(sb + ALO + ao, al[mi][0], al[mi][1], al[mi][2], al[mi][3]);
            }
#pragma unroll
            for (int mi = 0; mi < MF; mi++)
#pragma unroll
                for (int ni = 0; ni < NF; ni++)
                    mma16816(acc[mi][ni], al[mi],
                             bx[ni >> 1][ni & 1], bx[ni >> 1][(ni & 1) + 2]);
            // Ah * Bl  (reuse bx regs)
#pragma unroll
            for (int j = 0; j < NF / 2; j++) {
                const u32 row = (u32)(wN * NTw + j * 16 + rfr);
                const u32 bo  = row * 128 + ((kch ^ (row & 7)) << 4);
                ldm4(sb + BLO + bo, bx[j][0], bx[j][1], bx[j][2], bx[j][3]);
            }
#pragma unroll
            for (int mi = 0; mi < MF; mi++)
#pragma unroll
                for (int ni = 0; ni < NF; ni++)
                    mma16816(acc[mi][ni], ah[mi],
                             bx[ni >> 1][ni & 1], bx[ni >> 1][(ni & 1) + 2]);
        }
        __syncthreads();
    }

    // ---- epilogue ----
    const int gid = lane >> 2, t4 = lane & 3;
#pragma unroll
    for (int mi = 0; mi < MF; mi++) {
#pragma unroll
        for (int h = 0; h < 2; h++) {
            const int m = m0 + wM * MT + mi * 16 + gid + h * 8;
#pragma unroll
            for (int ni = 0; ni < NF; ni++) {
                const int n = n0 + wN * NTw + ni * 8 + t4 * 2;
                float v0 = acc[mi][ni][h * 2 + 0];
                float v1 = acc[mi][ni][h * 2 + 1];

                if (EPI == 0) {
                    const int b = m >> 10, tok = m & 1023;
                    const int hd = n >> 6, d = n & 63;
                    float2 o = make_float2(v0 + bias[n], v1 + bias[n + 1]);
                    *(float2*)(out0 + (((size_t)(b * Hh + hd) * NSEQ) + tok) * DHd + d) = o;
                } else if (EPI == 7) {
                    const int b = m >> 10, tok = m & 1023;
                    const int hd = n >> 6, d = n & 63;
                    float* dst = out0 + ((size_t)(b * Hh + hd) * DHd) * NSEQ;
                    dst[(size_t)d * NSEQ + tok]       = v0 + bias[n];
                    dst[(size_t)(d + 1) * NSEQ + tok] = v1 + bias[n + 1];
                } else if (EPI == 2) {
                    *(float2*)(out0 + (size_t)m * DMOD + n) = make_float2(v0, v1);
                } else if (EPI == 6) {
                    *(float2*)(out0 + (size_t)m * DMOD + n) =
                        make_float2(v0 + bias[n], v1 + bias[n + 1]);
                } else if (EPI == 3) {
                    const float bb0 = s0[0], lam = s1[0];
                    float p0 = 1.0f / (1.0f + __expf(-(v0 + bb0)));
                    float p1 = 1.0f / (1.0f + __expf(-(v1 + bb0)));
                    const size_t idx = ((size_t)z * NSEQ + m) * NSEQ + n;
                    *(float2*)(out0 + idx) = make_float2(p0, p1);
                    *(float2*)(aux + idx) =
                        make_float2(lam * __logf(p0 + EPSF), lam * __logf(p1 + EPSF));
                } else if (EPI == 4) {
                    const int bz = z >> 4;
                    const size_t li = ((size_t)bz * NSEQ + m) * NSEQ + n;
                    float2 L = *(const float2*)(aux + li);
                    *(float2*)(out0 + ((size_t)z * NSEQ + m) * NSEQ + n) =
                        make_float2(v0 * 0.125f + L.x, v1 * 0.125f + L.y);
                } else if (EPI == 5) {
                    const int bz = z >> 4, hz = z & 15;
                    *(float2*)(out0 + ((size_t)bz * NSEQ + m) * DMOD + hz * DHd + n) =
                        make_float2(v0, v1);
                }
            }
        }
    }
}

// ---------------------------------------------------------------------------
__global__ void transpose_wb(const float* __restrict__ in, float* __restrict__ out)
{
    __shared__ float t[32][33];
    const int tx = threadIdx.x;
    const int x = blockIdx.x * 32 + tx;           // n (col of in)
    for (int i = threadIdx.y; i < 32; i += 8)
        t[i][tx] = in[(size_t)(blockIdx.y * 32 + i) * DMOD + x];
    __syncthreads();
    const int ox = blockIdx.y * 32 + tx;          // k (col of out)
    for (int i = threadIdx.y; i < 32; i += 8)
        out[(size_t)(blockIdx.x * 32 + i) * DMOD + ox] = t[tx][i];
}

// ---------------------------------------------------------------------------
__global__ __launch_bounds__(256)
void softmax_rows(float* __restrict__ att)
{
    const size_t row = (size_t)blockIdx.x * 8 + (threadIdx.x >> 5);
    const int lane = threadIdx.x & 31;
    float4* p4 = (float4*)(att + row * 1024);
    float4 v[8];
    float mx = -3.4e38f;
#pragma unroll
    for (int i = 0; i < 8; i++) {
        v[i] = p4[lane + 32 * i];
        mx = fmaxf(mx, fmaxf(fmaxf(v[i].x, v[i].y), fmaxf(v[i].z, v[i].w)));
    }
#pragma unroll
    for (int o = 16; o > 0; o >>= 1)
        mx = fmaxf(mx, __shfl_xor_sync(0xffffffffu, mx, o));
    float s = 0.0f;
#pragma unroll
    for (int i = 0; i < 8; i++) {
        v[i].x = __expf(v[i].x - mx); v[i].y = __expf(v[i].y - mx);
        v[i].z = __expf(v[i].z - mx); v[i].w = __expf(v[i].w - mx);
        s += v[i].x + v[i].y + v[i].z + v[i].w;
    }
#pragma unroll
    for (int o = 16; o > 0; o >>= 1)
        s += __shfl_xor_sync(0xffffffffu, s, o);
    const float inv = 1.0f / s;
#pragma unroll
    for (int i = 0; i < 8; i++) {
        v[i].x *= inv; v[i].y *= inv; v[i].z *= inv; v[i].w *= inv;
        p4[lane + 32 * i] = v[i];
    }
}

// ---------------------------------------------------------------------------
extern "C" void kernel_launch(void* const* d_in, const int* in_sizes, int n_in,
                              void* d_out, int out_size)
{
    const float* queries = (const float*)d_in[0];
    const float* keys    = (const float*)d_in[1];
    const float* values  = (const float*)d_in[2];
    const float* Wq = (const float*)d_in[3];  const float* bq = (const float*)d_in[4];
    const float* Wk = (const float*)d_in[5];  const float* bk = (const float*)d_in[6];
    const float* Wv = (const float*)d_in[7];  const float* bv = (const float*)d_in[8];
    const float* Wo = (const float*)d_in[9];  const float* bo = (const float*)d_in[10];
    const float* Wb = (const float*)d_in[11]; const float* bb = (const float*)d_in[12];
    const float* lam = (const float*)d_in[13];

    float* out_main = (float*)d_out;
    float* att      = out_main + (size_t)Bb * NSEQ * DMOD;
    float* Pout     = att + (size_t)Bb * Hh * NSEQ * NSEQ;

    float *gQ, *gK, *gVt, *gXW, *gCAT, *gL, *gWbT;
    cudaGetSymbolAddress((void**)&gQ,   g_Q);
    cudaGetSymbolAddress((void**)&gK,   g_K);
    cudaGetSymbolAddress((void**)&gVt,  g_Vt);
    cudaGetSymbolAddress((void**)&gXW,  g_XW);
    cudaGetSymbolAddress((void**)&gCAT, g_CAT);
    cudaGetSymbolAddress((void**)&gL,   g_L);
    cudaGetSymbolAddress((void**)&gWbT, g_WbT);

    const int SM128 = 65536, SM64 = 49152;
    cudaFuncSetAttribute(hmma_gemm<128,0>, cudaFuncAttributeMaxDynamicSharedMemorySize, SM128);
    cudaFuncSetAttribute(hmma_gemm<128,2>, cudaFuncAttributeMaxDynamicSharedMemorySize, SM128);
    cudaFuncSetAttribute(hmma_gemm<128,3>, cudaFuncAttributeMaxDynamicSharedMemorySize, SM128);
    cudaFuncSetAttribute(hmma_gemm<128,4>, cudaFuncAttributeMaxDynamicSharedMemorySize, SM128);
    cudaFuncSetAttribute(hmma_gemm<64 ,5>, cudaFuncAttributeMaxDynamicSharedMemorySize, SM64);
    cudaFuncSetAttribute(hmma_gemm<128,6>, cudaFuncAttributeMaxDynamicSharedMemorySize, SM128);
    cudaFuncSetAttribute(hmma_gemm<128,7>, cudaFuncAttributeMaxDynamicSharedMemorySize, SM128);

    dim3 blk(256);
    dim3 gP(DMOD / 128, MR / 128, 1);   // 8 x 64

    transpose_wb<<<dim3(32, 32), dim3(32, 8)>>>(Wb, gWbT);

    // projections (NT): Q, K -> [z][tok][d];  V -> [z][d][tok]
    hmma_gemm<128,0><<<gP, blk, SM128>>>(queries, Wq, DMOD, 0, 0, gQ,  nullptr, bq, nullptr, nullptr);
    hmma_gemm<128,0><<<gP, blk, SM128>>>(keys,    Wk, DMOD, 0, 0, gK,  nullptr, bk, nullptr, nullptr);
    hmma_gemm<128,7><<<gP, blk, SM128>>>(values,  Wv, DMOD, 0, 0, gVt, nullptr, bv, nullptr, nullptr);
    // xW = queries @ Wb  (B = WbT[n][k])
    hmma_gemm<128,2><<<gP, blk, SM128>>>(queries, gWbT, DMOD, 0, 0, gXW, nullptr, nullptr, nullptr, nullptr);
    // P = sigmoid(xW q^T + bb), L = lam*log(P+eps)
    hmma_gemm<128,3><<<dim3(8, 8, Bb), blk, SM128>>>(
        gXW, queries, DMOD, (long long)NSEQ * DMOD, (long long)NSEQ * DMOD,
        Pout, gL, nullptr, bb, lam);
    // logits = 0.125 * Q K^T + L
    hmma_gemm<128,4><<<dim3(8, 8, Bb * Hh), blk, SM128>>>(
        gQ, gK, DHd, (long long)NSEQ * DHd, (long long)NSEQ * DHd,
        att, gL, nullptr, nullptr, nullptr);
    // softmax in place
    softmax_rows<<<(Bb * Hh * NSEQ) / 8, 256>>>(att);
    // CAT = att @ V   (B = Vt[d][tok])
    hmma_gemm<64,5><<<dim3(1, 8, Bb * Hh), blk, SM64>>>(
        att, gVt, NSEQ, (long long)NSEQ * NSEQ, (long long)DHd * NSEQ,
        gCAT, nullptr, nullptr, nullptr, nullptr);
    // out = CAT @ Wo^T + bo
    hmma_gemm<128,6><<<gP, blk, SM128>>>(gCAT, Wo, DMOD, 0, 0, out_main, nullptr, bo, nullptr, nullptr);

    (void)in_sizes; (void)n_in; (void)out_size;
}